// round 4
// baseline (speedup 1.0000x reference)
#include <cuda_runtime.h>

// CTC forward loss (alpha recursion), B=32, T=1000, V=1024, L=100, S=2L+1=201.
// One CTA per batch element; one thread per extended-label lane.
// Double-buffered shared alpha -> one barrier per time step.
// 2-deep software prefetch of the scattered emission gather.
//
// R3 bugfix: shared alpha is padded to cover ALL 224 lanes' unguarded reads
// (lanes 201..223 read alpha[cur][s+2] up to index 225; previous size 203
// was an out-of-window shared read -> illegal memory access).

#define Bc 32
#define Tc 1000
#define Vc 1024
#define Lc 100
#define Sc 201          // 2*L + 1
#define NEGV (-1e9f)
#define EPSV (1e-7f)
#define NTHREADS 224    // 7 warps; lanes 0..200 active
#define APAD (NTHREADS + 8)   // covers reads at [s+2] for all s < NTHREADS

__device__ float g_loss[Bc];

__global__ __launch_bounds__(NTHREADS, 1)
void ctc_alpha_kernel(const float* __restrict__ pred,
                      const int*   __restrict__ lenA,
                      const int*   __restrict__ lenB,
                      const int*   __restrict__ labels)
{
    __shared__ float alpha[2][APAD];   // [*][0..1] = NEG padding, lane s at [s+2]

    const int b = blockIdx.x;
    const int s = threadIdx.x;
    const float* pb = pred + (size_t)b * Tc * Vc;

    // Disambiguate the two length vectors by value (ranges are disjoint:
    // input_len in [500,1000], label_len in [50,100]).
    const int la = lenA[b];
    const int lb = lenB[b];
    const int ilen = max(la, lb);                  // input length
    const int llen = min(max(min(la, lb), 1), Lc); // label length, clamped

    const bool active = (s < Sc);
    const bool valid  = active && (s < 2 * llen + 1);

    // Extended label: even s -> blank (V-1), odd s -> labels[s/2].
    int  ext   = Vc - 1;
    bool allow = false;   // allow_skip: ext != blank && ext != ext[s-2]
    if (active && (s & 1)) {
        ext = labels[b * Lc + (s >> 1)] & (Vc - 1);
        allow = (s < 2) ? true : (ext != (labels[b * Lc + (s >> 1) - 1] & (Vc - 1)));
    }

    // Initialize the WHOLE padded array in both buffers (all lanes read it).
    alpha[0][s] = NEGV;  alpha[1][s] = NEGV;
    if (s < APAD - NTHREADS) {
        alpha[0][NTHREADS + s] = NEGV;
        alpha[1][NTHREADS + s] = NEGV;
    }
    __syncthreads();

    // ---- t = 0 init ----
    const float* pp = pb + ext;                 // walks down t with stride V
    float e0 = active ? __logf(pp[0] + EPSV) : 0.0f;
    if (active) alpha[0][s + 2] = (valid && s < 2) ? e0 : NEGV;

    // ---- 2-deep prefetch of emission probabilities ----
    float p0 = active ? pp[1 * Vc] : 0.0f;      // for t = 1
    float p1 = active ? pp[2 * Vc] : 0.0f;      // for t = 2
    pp += 3 * Vc;

    __syncthreads();

    int cur = 0;
    #pragma unroll 1
    for (int t = 1; t < Tc; ++t) {
        // prefetch emission for t+2
        float pn = 0.0f;
        if (active && (t + 2) < Tc) pn = *pp;
        pp += Vc;

        // emission log-prob for this step — independent of alpha chain
        float el = __logf(p0 + EPSV);

        float a  = alpha[cur][s + 2];           // alpha[s]
        float bb = alpha[cur][s + 1];           // alpha[s-1]
        float cc = allow ? alpha[cur][s] : NEGV;// alpha[s-2] (skip)

        float m   = fmaxf(a, fmaxf(bb, cc));
        float sum = __expf(a - m) + __expf(bb - m) + __expf(cc - m);
        float nv  = m + __logf(sum) + el;

        // valid lanes advance while t < input_length; otherwise hold.
        float res = (valid && t < ilen) ? nv : a;

        if (active) alpha[cur ^ 1][s + 2] = res;
        __syncthreads();
        cur ^= 1;

        p0 = p1; p1 = pn;
    }

    if (s == 0) {
        float al = alpha[cur][2 * llen - 1 + 2];   // last label lane
        float ab = alpha[cur][2 * llen + 2];       // trailing blank lane
        float m  = fmaxf(al, ab);
        float ll = m + __logf(__expf(al - m) + __expf(ab - m));
        g_loss[b] = -ll;
    }
}

__global__ void ctc_reduce_kernel(float* __restrict__ out)
{
    float v = g_loss[threadIdx.x];
    #pragma unroll
    for (int o = 16; o; o >>= 1)
        v += __shfl_xor_sync(0xffffffffu, v, o);
    if (threadIdx.x == 0) out[0] = v * (1.0f / (float)Bc);
}

extern "C" void kernel_launch(void* const* d_in, const int* in_sizes, int n_in,
                              void* d_out, int out_size)
{
    // Rank the first 4 inputs by size (descending). Robust to ordering and to
    // in_sizes being element counts or bytes.
    int idx[4] = {0, 1, 2, 3};
    for (int i = 0; i < 3; ++i)
        for (int j = i + 1; j < 4; ++j)
            if ((long long)in_sizes[idx[j]] > (long long)in_sizes[idx[i]]) {
                int t = idx[i]; idx[i] = idx[j]; idx[j] = t;
            }

    const float* pred   = (const float*)d_in[idx[0]];  // largest: [B,T,V]
    const int*   labels = (const int*)  d_in[idx[1]];  // 2nd:     [B,L]
    const int*   lenA   = (const int*)  d_in[idx[2]];  // length vectors
    const int*   lenB   = (const int*)  d_in[idx[3]];

    float* out = (float*)d_out;

    ctc_alpha_kernel<<<Bc, NTHREADS>>>(pred, lenA, lenB, labels);
    ctc_reduce_kernel<<<1, 32>>>(out);
}

// round 6
// speedup vs baseline: 2.7476x; 2.7476x over previous
#include <cuda_runtime.h>

// CTC forward loss (alpha recursion), B=32, T=1000, V=1024, L=100, S=2L+1=201.
// Log-domain DP identical to the R4 passing kernel; single change:
// the scattered emission gather is prefetched 8-deep into registers
// (lookahead ~8 steps >> memory latency), and the loop stops at t = ilen
// (exactly equivalent to the reference's freeze).

#define Bc 32
#define Tc 1000
#define Vc 1024
#define Lc 100
#define Sc 201          // 2*L + 1
#define NEGV (-1e9f)
#define EPSV (1e-7f)
#define NTHREADS 224    // 7 warps; lanes 0..200 active
#define APAD (NTHREADS + 8)

__device__ float g_loss[Bc];

__global__ __launch_bounds__(NTHREADS, 1)
void ctc_alpha_kernel(const float* __restrict__ pred,
                      const int*   __restrict__ lenA,
                      const int*   __restrict__ lenB,
                      const int*   __restrict__ labels)
{
    __shared__ float alpha[2][APAD];   // lane s lives at [s+2]; [0..1] = NEG pad

    const int b = blockIdx.x;
    const int s = threadIdx.x;

    // Disambiguate the two length vectors by value range
    // (input_len in [500,1000], label_len in [50,100] -- disjoint).
    const int la = lenA[b], lb = lenB[b];
    const int ilen = min(max(max(la, lb), 1), Tc);
    const int llen = min(max(min(la, lb), 1), Lc);

    const bool active = (s < Sc);
    const bool valid  = active && (s < 2 * llen + 1);

    // Extended label: even s -> blank (V-1), odd s -> labels[s/2].
    int  ext   = Vc - 1;
    bool allow = false;   // skip transition allowed
    if (active && (s & 1)) {
        ext = labels[b * Lc + (s >> 1)] & (Vc - 1);
        allow = (s < 2) ? true : (ext != (labels[b * Lc + (s >> 1) - 1] & (Vc - 1)));
    }

    const float* eb = pred + (size_t)b * Tc * Vc + ext;   // stride V walk over t

    // init both buffers (full padded range) to NEG
    alpha[0][s] = NEGV;  alpha[1][s] = NEGV;
    if (s < APAD - NTHREADS) {
        alpha[0][NTHREADS + s] = NEGV;
        alpha[1][NTHREADS + s] = NEGV;
    }
    __syncthreads();

    // ---- t = 0 ----
    const float e0 = __logf(eb[0] + EPSV);
    alpha[0][s + 2] = (valid && s < 2) ? e0 : NEGV;

    // ---- preload emissions (raw probs) for t = 1..8 ----
    float er[8];
    #pragma unroll
    for (int j = 0; j < 8; ++j) {
        int tn = 1 + j; if (tn > Tc - 1) tn = Tc - 1;
        er[j] = eb[(size_t)tn * Vc];
    }
    __syncthreads();

    int cur = 0;
    int t   = 1;

    // ---- full 8-step windows (steps t..t+7, all < ilen) ----
    while (t + 8 <= ilen) {
        #pragma unroll
        for (int j = 0; j < 8; ++j) {
            // issue prefetch for step t+8+j (clamped; unused slots harmless)
            int tn = t + 8 + j; if (tn > Tc - 1) tn = Tc - 1;
            const float pn = eb[(size_t)tn * Vc];

            // emission log-prob: off the alpha critical path
            const float el = __logf(er[j] + EPSV);

            const float a  = alpha[cur][s + 2];
            const float bb = alpha[cur][s + 1];
            const float cc = allow ? alpha[cur][s] : NEGV;

            const float m   = fmaxf(a, fmaxf(bb, cc));
            const float sum = __expf(a - m) + __expf(bb - m) + __expf(cc - m);
            const float nv  = m + __logf(sum) + el;

            alpha[cur ^ 1][s + 2] = valid ? nv : NEGV;
            __syncthreads();
            cur ^= 1;

            er[j] = pn;
        }
        t += 8;
    }

    // ---- tail (< 8 steps); emissions already resident in er[] ----
    for (int j = 0; t < ilen; ++t, ++j) {
        const float el = __logf(er[j] + EPSV);

        const float a  = alpha[cur][s + 2];
        const float bb = alpha[cur][s + 1];
        const float cc = allow ? alpha[cur][s] : NEGV;

        const float m   = fmaxf(a, fmaxf(bb, cc));
        const float sum = __expf(a - m) + __expf(bb - m) + __expf(cc - m);
        const float nv  = m + __logf(sum) + el;

        alpha[cur ^ 1][s + 2] = valid ? nv : NEGV;
        __syncthreads();
        cur ^= 1;
    }

    if (s == 0) {
        const float a1 = alpha[cur][2 * llen - 1 + 2];   // last label lane
        const float a2 = alpha[cur][2 * llen + 2];       // trailing blank lane
        const float m  = fmaxf(a1, a2);
        const float ll = m + __logf(__expf(a1 - m) + __expf(a2 - m));
        g_loss[b] = -ll;
    }
}

__global__ void ctc_reduce_kernel(float* __restrict__ out)
{
    float v = g_loss[threadIdx.x];
    #pragma unroll
    for (int o = 16; o; o >>= 1)
        v += __shfl_xor_sync(0xffffffffu, v, o);
    if (threadIdx.x == 0) out[0] = v * (1.0f / (float)Bc);
}

extern "C" void kernel_launch(void* const* d_in, const int* in_sizes, int n_in,
                              void* d_out, int out_size)
{
    // Identify inputs by size rank (robust to ordering / bytes-vs-elems).
    int idx[4] = {0, 1, 2, 3};
    for (int i = 0; i < 3; ++i)
        for (int j = i + 1; j < 4; ++j)
            if ((long long)in_sizes[idx[j]] > (long long)in_sizes[idx[i]]) {
                int tmp = idx[i]; idx[i] = idx[j]; idx[j] = tmp;
            }

    const float* pred   = (const float*)d_in[idx[0]];  // [B,T,V]
    const int*   labels = (const int*)  d_in[idx[1]];  // [B,L]
    const int*   lenA   = (const int*)  d_in[idx[2]];  // length vectors
    const int*   lenB   = (const int*)  d_in[idx[3]];

    float* out = (float*)d_out;

    ctc_alpha_kernel<<<Bc, NTHREADS>>>(pred, lenA, lenB, labels);
    ctc_reduce_kernel<<<1, 32>>>(out);
}

// round 7
// speedup vs baseline: 3.0315x; 1.1033x over previous
#include <cuda_runtime.h>

// CTC forward loss. B=32, T=1000, V=1024, L=100, S=2L+1=201.
//
// Pass 1 (parallel): g_emit[b][t][s] = log(pred[b][t][ext[s]] + EPS)
//   -- hoists the scattered V-dim gather AND the per-step __logf out of the
//      serial DP loop. Coalesced 224-float rows, ~28.7 MB scratch.
// Pass 2 (serial DP): R6's proven log-domain alpha recursion, unchanged math;
//   emission loads are now coalesced (1 line/warp/step), 8-deep prefetched.
// Pass 3: mean reduce.

#define Bc 32
#define Tc 1000
#define Vc 1024
#define Lc 100
#define Sc 201          // 2*L + 1
#define NEGV (-1e9f)
#define EPSV (1e-7f)
#define NTHREADS 224    // 7 warps; lanes 0..200 active
#define APAD (NTHREADS + 8)
#define ESTR 224        // emission row stride (7 x 128B lines)

__device__ float g_emit[(size_t)Bc * Tc * ESTR];   // ~28.7 MB scratch (L2-resident)
__device__ float g_loss[Bc];

// ---------------- Pass 1: emission gather + log (parallel) ----------------
__global__ __launch_bounds__(NTHREADS)
void ctc_emit_kernel(const float* __restrict__ pred,
                     const int*   __restrict__ lenA,
                     const int*   __restrict__ lenB,
                     const int*   __restrict__ labels)
{
    const int t = blockIdx.x;
    const int b = blockIdx.y;
    const int s = threadIdx.x;

    const int ilen = min(max(max(lenA[b], lenB[b]), 1), Tc);
    if (t >= ilen) return;                 // DP never consumes t >= ilen

    int ext = Vc - 1;                      // blank
    if ((s & 1) && s < Sc) ext = labels[b * Lc + (s >> 1)] & (Vc - 1);

    const float p = pred[((size_t)b * Tc + t) * Vc + ext];
    g_emit[((size_t)b * Tc + t) * ESTR + s] = __logf(p + EPSV);
}

// ---------------- Pass 2: serial DP (log domain, identical to R6) ----------
__global__ __launch_bounds__(NTHREADS, 1)
void ctc_alpha_kernel(const int* __restrict__ lenA,
                      const int* __restrict__ lenB,
                      const int* __restrict__ labels)
{
    __shared__ float alpha[2][APAD];   // lane s lives at [s+2]; [0..1] = NEG pad

    const int b = blockIdx.x;
    const int s = threadIdx.x;

    // Disambiguate the two length vectors by value range
    // (input_len in [500,1000], label_len in [50,100] -- disjoint).
    const int la = lenA[b], lb = lenB[b];
    const int ilen = min(max(max(la, lb), 1), Tc);
    const int llen = min(max(min(la, lb), 1), Lc);

    const bool active = (s < Sc);
    const bool valid  = active && (s < 2 * llen + 1);

    bool allow = false;   // skip transition allowed
    if (active && (s & 1)) {
        const int e0 = labels[b * Lc + (s >> 1)] & (Vc - 1);
        allow = (s < 2) ? true
              : (e0 != (labels[b * Lc + (s >> 1) - 1] & (Vc - 1)));
    }

    const float* eb = g_emit + (size_t)b * Tc * ESTR + s;   // coalesced rows

    // init both buffers (full padded range) to NEG
    alpha[0][s] = NEGV;  alpha[1][s] = NEGV;
    if (s < APAD - NTHREADS) {
        alpha[0][NTHREADS + s] = NEGV;
        alpha[1][NTHREADS + s] = NEGV;
    }
    __syncthreads();

    // ---- t = 0 ----
    alpha[0][s + 2] = (valid && s < 2) ? eb[0] : NEGV;

    // ---- preload log-emissions for t = 1..8 ----
    float er[8];
    #pragma unroll
    for (int j = 0; j < 8; ++j) {
        int tn = 1 + j; if (tn > Tc - 1) tn = Tc - 1;
        er[j] = eb[(size_t)tn * ESTR];
    }
    __syncthreads();

    int cur = 0;
    int t   = 1;

    // ---- full 8-step windows (steps t..t+7, all < ilen) ----
    while (t + 8 <= ilen) {
        #pragma unroll
        for (int j = 0; j < 8; ++j) {
            // issue prefetch for step t+8+j (clamped; unused slots harmless)
            int tn = t + 8 + j; if (tn > Tc - 1) tn = Tc - 1;
            const float pn = eb[(size_t)tn * ESTR];

            const float el = er[j];

            const float a  = alpha[cur][s + 2];
            const float bb = alpha[cur][s + 1];
            const float cc = allow ? alpha[cur][s] : NEGV;

            const float m   = fmaxf(a, fmaxf(bb, cc));
            const float sum = __expf(a - m) + __expf(bb - m) + __expf(cc - m);
            const float nv  = m + __logf(sum) + el;

            alpha[cur ^ 1][s + 2] = valid ? nv : NEGV;
            __syncthreads();
            cur ^= 1;

            er[j] = pn;
        }
        t += 8;
    }

    // ---- tail (< 8 steps); emissions already resident in er[] ----
    for (int j = 0; t < ilen; ++t, ++j) {
        const float el = er[j];

        const float a  = alpha[cur][s + 2];
        const float bb = alpha[cur][s + 1];
        const float cc = allow ? alpha[cur][s] : NEGV;

        const float m   = fmaxf(a, fmaxf(bb, cc));
        const float sum = __expf(a - m) + __expf(bb - m) + __expf(cc - m);
        const float nv  = m + __logf(sum) + el;

        alpha[cur ^ 1][s + 2] = valid ? nv : NEGV;
        __syncthreads();
        cur ^= 1;
    }

    if (s == 0) {
        const float a1 = alpha[cur][2 * llen - 1 + 2];   // last label lane
        const float a2 = alpha[cur][2 * llen + 2];       // trailing blank lane
        const float m  = fmaxf(a1, a2);
        const float ll = m + __logf(__expf(a1 - m) + __expf(a2 - m));
        g_loss[b] = -ll;
    }
}

// ---------------- Pass 3: mean ----------------
__global__ void ctc_reduce_kernel(float* __restrict__ out)
{
    float v = g_loss[threadIdx.x];
    #pragma unroll
    for (int o = 16; o; o >>= 1)
        v += __shfl_xor_sync(0xffffffffu, v, o);
    if (threadIdx.x == 0) out[0] = v * (1.0f / (float)Bc);
}

extern "C" void kernel_launch(void* const* d_in, const int* in_sizes, int n_in,
                              void* d_out, int out_size)
{
    // Identify inputs by size rank (robust to ordering / bytes-vs-elems).
    int idx[4] = {0, 1, 2, 3};
    for (int i = 0; i < 3; ++i)
        for (int j = i + 1; j < 4; ++j)
            if ((long long)in_sizes[idx[j]] > (long long)in_sizes[idx[i]]) {
                int tmp = idx[i]; idx[i] = idx[j]; idx[j] = tmp;
            }

    const float* pred   = (const float*)d_in[idx[0]];  // [B,T,V]
    const int*   labels = (const int*)  d_in[idx[1]];  // [B,L]
    const int*   lenA   = (const int*)  d_in[idx[2]];  // length vectors
    const int*   lenB   = (const int*)  d_in[idx[3]];

    float* out = (float*)d_out;

    dim3 g1(Tc, Bc);
    ctc_emit_kernel<<<g1, NTHREADS>>>(pred, lenA, lenB, labels);
    ctc_alpha_kernel<<<Bc, NTHREADS>>>(lenA, lenB, labels);
    ctc_reduce_kernel<<<1, 32>>>(out);
}